// round 3
// baseline (speedup 1.0000x reference)
#include <cuda_runtime.h>
#include <math.h>

#define BATCH 8
#define HH 180
#define WW 180
#define NF 24
#define KSZ 5
#define NBR 31
#define NPIX (BATCH*HH*WW)

#define TBL_N 65536
#define TBL_LO (-4.0f)
#define TBL_SCALE ((float)TBL_N / 8.0f)   /* 8192 per unit */

// -------- device scratch (no allocations allowed) --------
__device__ float2 g_table[TBL_N];               // {phi(x_i), phi(x_{i+1})-phi(x_i)}
__device__ double g_part[256];                  // deterministic reduction partials
__device__ float  g_invM;
__device__ float  g_sp[BATCH*NF*HH*WW];         // scaled_phi intermediate (~25 MB)

// ============================================================
// Kernel 1: weighted sum of u  ->  sum(u_sigma) via border weights
//   sum(avgpool3x3(u)) = sum_p u[p] * wy(p)*wx(p) / 9,  w=2 at border else 3
// ============================================================
__global__ __launch_bounds__(256) void k_reduce(const float* __restrict__ u) {
    __shared__ double sred[256];
    double acc = 0.0;
    for (int i = blockIdx.x * 256 + threadIdx.x; i < NPIX; i += 256 * 256) {
        int x = i % WW;
        int y = (i / WW) % HH;
        float wy = (y == 0 || y == HH - 1) ? 2.0f : 3.0f;
        float wx = (x == 0 || x == WW - 1) ? 2.0f : 3.0f;
        acc += (double)(u[i] * (wy * wx));
    }
    sred[threadIdx.x] = acc;
    __syncthreads();
    for (int s = 128; s > 0; s >>= 1) {
        if (threadIdx.x < s) sred[threadIdx.x] += sred[threadIdx.x + s];
        __syncthreads();
    }
    if (threadIdx.x == 0) g_part[blockIdx.x] = sred[0];
}

// ============================================================
// Kernel 2: build RBF table; thread (0,0) finalizes 1/M
// ============================================================
__global__ __launch_bounds__(256) void k_table(const float* __restrict__ mu,
                                               const float* __restrict__ wts) {
    int i = blockIdx.x * 256 + threadIdx.x;
    const float h = 8.0f / (float)TBL_N;
    float x0 = TBL_LO + (float)i * h;
    float x1 = x0 + h;
    float v0 = 0.0f, v1 = 0.0f;
    #pragma unroll 1
    for (int j = 0; j < NBR; j++) {
        float m = mu[j], w = wts[j];
        float d0 = x0 - m, d1 = x1 - m;
        v0 += w * expf(-d0 * d0 * 50.0f);   // 1/(2*gamma^2) = 50
        v1 += w * expf(-d1 * d1 * 50.0f);
    }
    g_table[i] = make_float2(v0, v1 - v0);
    if (i == 0) {
        double s = 0.0;
        for (int k = 0; k < 256; k++) s += g_part[k];
        double M = s / 9.0 / (double)NPIX + 0.001;
        g_invM = (float)(1.0 / M);
    }
}

// ============================================================
// Kernel 3: conv1 (1->24, 5x5, pad 2) + u_sigma + RBF lookup + scale
//   grid (6,6,8), 256 threads; 32x32 output tile, 1x4 strips per thread
// ============================================================
__global__ __launch_bounds__(256) void k_conv1(const float* __restrict__ u,
                                               const float* __restrict__ filt) {
    __shared__ float su[36 * 37];
    __shared__ float sw[NF * 25];
    const int b = blockIdx.z;
    const int ox0 = blockIdx.x * 32, oy0 = blockIdx.y * 32;
    const int tid = threadIdx.x;

    for (int i = tid; i < NF * 25; i += 256) sw[i] = filt[i];

    const float* ub = u + b * HH * WW;
    for (int i = tid; i < 36 * 36; i += 256) {
        int sy = i / 36, sx = i % 36;
        int gy = oy0 - 2 + sy, gx = ox0 - 2 + sx;
        float v = 0.0f;
        if (gy >= 0 && gy < HH && gx >= 0 && gx < WW) v = ub[gy * WW + gx];
        su[sy * 37 + sx] = v;
    }
    __syncthreads();

    const int r  = tid >> 3;       // 0..31 row within tile
    const int sc = tid & 7;        // 0..7 strip of 4 cols
    const int gy = oy0 + r;
    const int gx = ox0 + sc * 4;
    if (gy >= HH || gx >= WW) return;   // 180 mod 32 == 20: strips are never partial

    float uwin[5][8];
    #pragma unroll
    for (int i = 0; i < 5; i++)
        #pragma unroll
        for (int j = 0; j < 8; j++)
            uwin[i][j] = su[(r + i) * 37 + sc * 4 + j];

    // u_sigma * (1/9) * (1/M)   (rows r-1..r+1 = uwin rows 1..3)
    float s4[4];
    {
        float cs[6];
        #pragma unroll
        for (int j = 0; j < 6; j++)
            cs[j] = uwin[1][j + 1] + uwin[2][j + 1] + uwin[3][j + 1];
        float sm = g_invM * (1.0f / 9.0f);
        #pragma unroll
        for (int p = 0; p < 4; p++)
            s4[p] = (cs[p] + cs[p + 1] + cs[p + 2]) * sm;
    }

    float* outb = g_sp + (size_t)(b * NF) * (HH * WW) + gy * WW + gx;

    #pragma unroll 1
    for (int c = 0; c < NF; c++) {
        float w[25];
        #pragma unroll
        for (int k = 0; k < 25; k++) w[k] = sw[c * 25 + k];
        float a0 = 0.f, a1 = 0.f, a2 = 0.f, a3 = 0.f;
        #pragma unroll
        for (int dy = 0; dy < 5; dy++)
            #pragma unroll
            for (int dx = 0; dx < 5; dx++) {
                float wk = w[dy * 5 + dx];
                a0 = fmaf(uwin[dy][dx + 0], wk, a0);
                a1 = fmaf(uwin[dy][dx + 1], wk, a1);
                a2 = fmaf(uwin[dy][dx + 2], wk, a2);
                a3 = fmaf(uwin[dy][dx + 3], wk, a3);
            }
        float accs[4] = {a0, a1, a2, a3};
        float o[4];
        #pragma unroll
        for (int p = 0; p < 4; p++) {
            float xs = (accs[p] - TBL_LO) * TBL_SCALE;
            xs = fminf(fmaxf(xs, 0.0f), (float)(TBL_N - 2) + 0.999f);
            int idx = (int)xs;
            float t = xs - (float)idx;
            float2 e = g_table[idx];
            o[p] = s4[p] * fmaf(t, e.y, e.x);
        }
        *reinterpret_cast<float4*>(outb + c * (HH * WW)) =
            make_float4(o[0], o[1], o[2], o[3]);
    }
}

// ============================================================
// Kernel 4: conv2 (24->1 with flipped kernels) + reaction + clip
// ============================================================
__global__ __launch_bounds__(256) void k_conv2(const float* __restrict__ u,
                                               const float* __restrict__ f,
                                               const float* __restrict__ filt,
                                               const float* __restrict__ lam,
                                               float* __restrict__ out) {
    __shared__ float sp[36 * 37];
    __shared__ float sw[NF * 25];
    const int b = blockIdx.z;
    const int ox0 = blockIdx.x * 32, oy0 = blockIdx.y * 32;
    const int tid = threadIdx.x;

    // flipped weights: swt[c][dy][dx] = filt[c][4-dy][4-dx]
    for (int i = tid; i < NF * 25; i += 256) {
        int c = i / 25, k = i % 25;
        sw[i] = filt[c * 25 + 24 - k];
    }

    const int r  = tid >> 3;
    const int sc = tid & 7;
    const int gy = oy0 + r;
    const int gx = ox0 + sc * 4;
    const bool active = (gy < HH && gx < WW);

    float acc[4] = {0.f, 0.f, 0.f, 0.f};
    const float* spb = g_sp + (size_t)(b * NF) * (HH * WW);

    #pragma unroll 1
    for (int c = 0; c < NF; c++) {
        __syncthreads();   // also orders sw init before first use
        const float* spc = spb + c * (HH * WW);
        for (int i = tid; i < 36 * 36; i += 256) {
            int sy = i / 36, sx = i % 36;
            int py = oy0 - 2 + sy, px = ox0 - 2 + sx;
            float v = 0.0f;
            if (py >= 0 && py < HH && px >= 0 && px < WW) v = spc[py * WW + px];
            sp[sy * 37 + sx] = v;
        }
        __syncthreads();
        if (active) {
            float w[25];
            #pragma unroll
            for (int k = 0; k < 25; k++) w[k] = sw[c * 25 + k];
            #pragma unroll
            for (int dy = 0; dy < 5; dy++) {
                float row[8];
                #pragma unroll
                for (int j = 0; j < 8; j++) row[j] = sp[(r + dy) * 37 + sc * 4 + j];
                #pragma unroll
                for (int dx = 0; dx < 5; dx++) {
                    float wk = w[dy * 5 + dx];
                    acc[0] = fmaf(row[dx + 0], wk, acc[0]);
                    acc[1] = fmaf(row[dx + 1], wk, acc[1]);
                    acc[2] = fmaf(row[dx + 2], wk, acc[2]);
                    acc[3] = fmaf(row[dx + 3], wk, acc[3]);
                }
            }
        }
    }

    if (active) {
        float lambda = lam[0];
        size_t off = (size_t)b * (HH * WW) + gy * WW + gx;
        float4 u4 = *reinterpret_cast<const float4*>(u + off);
        float4 f4 = *reinterpret_cast<const float4*>(f + off);
        float uu[4] = {u4.x, u4.y, u4.z, u4.w};
        float ff[4] = {f4.x, f4.y, f4.z, f4.w};
        float o[4];
        #pragma unroll
        for (int p = 0; p < 4; p++) {
            float reac = lambda * (uu[p] - ff[p]) / (uu[p] * uu[p] + 1e-3f);
            float v = uu[p] - acc[p] - reac;
            o[p] = fminf(fmaxf(v, 0.0f), 1.0f);
        }
        *reinterpret_cast<float4*>(out + off) = make_float4(o[0], o[1], o[2], o[3]);
    }
}

// ============================================================
extern "C" void kernel_launch(void* const* d_in, const int* in_sizes, int n_in,
                              void* d_out, int out_size) {
    const float* u    = (const float*)d_in[0];
    const float* f    = (const float*)d_in[1];
    const float* filt = (const float*)d_in[2];
    const float* lam  = (const float*)d_in[3];
    const float* mu   = (const float*)d_in[4];
    const float* wts  = (const float*)d_in[5];
    float* out = (float*)d_out;

    k_reduce<<<256, 256>>>(u);
    k_table<<<TBL_N / 256, 256>>>(mu, wts);
    dim3 grid(6, 6, BATCH);
    k_conv1<<<grid, 256>>>(u, filt);
    k_conv2<<<grid, 256>>>(u, f, filt, lam, out);
}

// round 4
// speedup vs baseline: 1.6585x; 1.6585x over previous
#include <cuda_runtime.h>
#include <math.h>

#define BATCH 8
#define HH 180
#define WW 180
#define NF 24
#define NBR 31
#define NPIX (BATCH*HH*WW)

#define TBL_N 16384
#define TBL_LO (-4.0f)
#define TBL_SCALE ((float)TBL_N / 8.0f)   /* 2048 per unit */

// -------- device scratch (no allocations allowed) --------
__device__ float  g_nodes[TBL_N + 1];     // phi(x_i) node values
__device__ double g_part[256];            // deterministic reduction partials
__device__ float  g_invM;

// ============================================================
// Kernel 1: weighted sum of u -> sum(u_sigma) via border weights
// ============================================================
__global__ __launch_bounds__(256) void k_reduce(const float* __restrict__ u) {
    __shared__ double sred[256];
    float facc = 0.0f;
    for (int i = blockIdx.x * 256 + threadIdx.x; i < NPIX; i += 256 * 256) {
        int x = i % WW;
        int y = (i / WW) % HH;
        float wy = (y == 0 || y == HH - 1) ? 2.0f : 3.0f;
        float wx = (x == 0 || x == WW - 1) ? 2.0f : 3.0f;
        facc += u[i] * (wy * wx);
    }
    sred[threadIdx.x] = (double)facc;
    __syncthreads();
    for (int s = 128; s > 0; s >>= 1) {
        if (threadIdx.x < s) sred[threadIdx.x] += sred[threadIdx.x + s];
        __syncthreads();
    }
    if (threadIdx.x == 0) g_part[blockIdx.x] = sred[0];
}

// ============================================================
// Kernel 2: build RBF node table (one endpoint per thread); finalize 1/M
// ============================================================
__global__ __launch_bounds__(256) void k_table(const float* __restrict__ mu,
                                               const float* __restrict__ wts) {
    int i = blockIdx.x * 256 + threadIdx.x;
    if (i <= TBL_N) {
        const float h = 8.0f / (float)TBL_N;
        float x = TBL_LO + (float)i * h;
        float v = 0.0f;
        #pragma unroll 1
        for (int j = 0; j < NBR; j++) {
            float d = x - mu[j];
            v += wts[j] * __expf(-d * d * 50.0f);   // 1/(2*gamma^2) = 50
        }
        g_nodes[i] = v;
    }
    if (i == 0) {
        double s = 0.0;
        for (int k = 0; k < 256; k++) s += g_part[k];
        double M = s / 9.0 / (double)NPIX + 0.001;
        g_invM = (float)(1.0 / M);
    }
}

// ============================================================
// Kernel 3: FUSED conv1 (1->24,5x5) + u_sigma/M + RBF lookup + conv2 (24->1,
//           flipped) + reaction + clip.
//   grid (6,6,8), 384 threads. Output tile 32x32; sphi tile 36x36 (halo 2);
//   u tile 40x40. Per channel: conv1 -> double-buffered smem -> 1 barrier ->
//   conv2 register accumulation.
// ============================================================
#define SPP 40   /* sphi row pitch (floats) — keeps float4 alignment */
#define UPP 41   /* u tile row pitch */

__global__ __launch_bounds__(384, 2) void k_fused(const float* __restrict__ u,
                                                  const float* __restrict__ f,
                                                  const float* __restrict__ filt,
                                                  const float* __restrict__ lam,
                                                  float* __restrict__ out) {
    __shared__ float su[40 * UPP];
    __shared__ float sphi[2][36 * SPP];
    __shared__ float sw1[NF * 25];
    __shared__ float sw2[NF * 25];

    const int b = blockIdx.z;
    const int ox0 = blockIdx.x * 32, oy0 = blockIdx.y * 32;
    const int tid = threadIdx.x;

    // weights: sw1 straight (conv1), sw2 flipped (conv2)
    for (int i = tid; i < NF * 25; i += 384) {
        int c = i / 25, k = i % 25;
        sw1[i] = filt[i];
        sw2[i] = filt[c * 25 + 24 - k];
    }

    // u tile: global rows oy0-4 .. oy0+35, cols ox0-4 .. ox0+35
    const float* ub = u + b * HH * WW;
    for (int i = tid; i < 40 * 40; i += 384) {
        int sy = i / 40, sx = i % 40;
        int gy = oy0 - 4 + sy, gx = ox0 - 4 + sx;
        float v = 0.0f;
        if (gy >= 0 && gy < HH && gx >= 0 && gx < WW) v = ub[gy * WW + gx];
        su[sy * UPP + sx] = v;
    }
    __syncthreads();

    // ---- conv1 lane setup (threads 0..323): 36x36 sphi tile, 1x4 strips ----
    const bool p1 = (tid < 324);
    const int ry = tid / 9;          // sphi row 0..35
    const int sx4 = (tid % 9) * 4;   // sphi col of strip
    float uwin[5][8];
    float s4[4];
    float msk[4];
    if (p1) {
        #pragma unroll
        for (int i = 0; i < 5; i++)
            #pragma unroll
            for (int j = 0; j < 8; j++)
                uwin[i][j] = su[(ry + i) * UPP + sx4 + j];
        // u_sigma/(9M) at the 4 strip pixels
        float cs[6];
        #pragma unroll
        for (int j = 0; j < 6; j++)
            cs[j] = uwin[1][j + 1] + uwin[2][j + 1] + uwin[3][j + 1];
        float sm = g_invM * (1.0f / 9.0f);
        int gy = oy0 - 2 + ry;
        bool rowok = (gy >= 0 && gy < HH);
        #pragma unroll
        for (int p = 0; p < 4; p++) {
            s4[p] = (cs[p] + cs[p + 1] + cs[p + 2]) * sm;
            int gx = ox0 - 2 + sx4 + p;
            msk[p] = (rowok && gx >= 0 && gx < WW) ? 1.0f : 0.0f;
        }
    }

    // ---- conv2 lane setup (threads 0..255): 32x32 output, 1x4 strips ----
    const bool p2 = (tid < 256);
    const int r2 = tid >> 3;
    const int c2 = (tid & 7) * 4;
    const int gy2 = oy0 + r2;
    const int gx2 = ox0 + c2;
    const bool active = p2 && (gy2 < HH) && (gx2 < WW);
    float acc[4] = {0.f, 0.f, 0.f, 0.f};

    // ---- channel loop: conv1 -> bar -> conv2 (double-buffered sphi) ----
    #pragma unroll 1
    for (int c = 0; c < NF; c++) {
        float* buf = sphi[c & 1];
        if (p1) {
            const float* w = sw1 + c * 25;
            float a0 = 0.f, a1 = 0.f, a2 = 0.f, a3 = 0.f;
            #pragma unroll
            for (int dy = 0; dy < 5; dy++)
                #pragma unroll
                for (int dx = 0; dx < 5; dx++) {
                    float wk = w[dy * 5 + dx];
                    a0 = fmaf(uwin[dy][dx + 0], wk, a0);
                    a1 = fmaf(uwin[dy][dx + 1], wk, a1);
                    a2 = fmaf(uwin[dy][dx + 2], wk, a2);
                    a3 = fmaf(uwin[dy][dx + 3], wk, a3);
                }
            float av[4] = {a0, a1, a2, a3};
            float o[4];
            #pragma unroll
            for (int p = 0; p < 4; p++) {
                float xs = (av[p] - TBL_LO) * TBL_SCALE;
                xs = fminf(fmaxf(xs, 0.0f), (float)TBL_N - 0.001f);
                int idx = (int)xs;
                float t = xs - (float)idx;
                float e0 = g_nodes[idx];
                float e1 = g_nodes[idx + 1];
                o[p] = s4[p] * fmaf(t, e1 - e0, e0) * msk[p];
            }
            *reinterpret_cast<float4*>(buf + ry * SPP + sx4) =
                make_float4(o[0], o[1], o[2], o[3]);
        }
        __syncthreads();
        if (active) {
            const float* w = sw2 + c * 25;
            #pragma unroll
            for (int dy = 0; dy < 5; dy++) {
                const float* row = buf + (r2 + dy) * SPP + c2;
                float4 ra = *reinterpret_cast<const float4*>(row);
                float4 rb = *reinterpret_cast<const float4*>(row + 4);
                float rr[8] = {ra.x, ra.y, ra.z, ra.w, rb.x, rb.y, rb.z, rb.w};
                #pragma unroll
                for (int dx = 0; dx < 5; dx++) {
                    float wk = w[dy * 5 + dx];
                    acc[0] = fmaf(rr[dx + 0], wk, acc[0]);
                    acc[1] = fmaf(rr[dx + 1], wk, acc[1]);
                    acc[2] = fmaf(rr[dx + 2], wk, acc[2]);
                    acc[3] = fmaf(rr[dx + 3], wk, acc[3]);
                }
            }
        }
    }

    // ---- epilogue: reaction + clip ----
    if (active) {
        float lambda = lam[0];
        size_t off = (size_t)b * (HH * WW) + gy2 * WW + gx2;
        float4 u4 = *reinterpret_cast<const float4*>(u + off);
        float4 f4 = *reinterpret_cast<const float4*>(f + off);
        float uu[4] = {u4.x, u4.y, u4.z, u4.w};
        float ff[4] = {f4.x, f4.y, f4.z, f4.w};
        float o[4];
        #pragma unroll
        for (int p = 0; p < 4; p++) {
            float reac = lambda * (uu[p] - ff[p]) / (uu[p] * uu[p] + 1e-3f);
            float v = uu[p] - acc[p] - reac;
            o[p] = fminf(fmaxf(v, 0.0f), 1.0f);
        }
        *reinterpret_cast<float4*>(out + off) = make_float4(o[0], o[1], o[2], o[3]);
    }
}

// ============================================================
extern "C" void kernel_launch(void* const* d_in, const int* in_sizes, int n_in,
                              void* d_out, int out_size) {
    const float* u    = (const float*)d_in[0];
    const float* f    = (const float*)d_in[1];
    const float* filt = (const float*)d_in[2];
    const float* lam  = (const float*)d_in[3];
    const float* mu   = (const float*)d_in[4];
    const float* wts  = (const float*)d_in[5];
    float* out = (float*)d_out;

    k_reduce<<<256, 256>>>(u);
    k_table<<<(TBL_N + 1 + 255) / 256, 256>>>(mu, wts);
    dim3 grid(6, 6, BATCH);
    k_fused<<<grid, 384>>>(u, f, filt, lam, out);
}